// round 6
// baseline (speedup 1.0000x reference)
#include <cuda_runtime.h>
#include <math.h>
#include <math_constants.h>

// Problem constants
#define NB 2
#define NS 2048
#define ND 2048
#define NH 16
#define DH 128
#define NM 4096   // NB*NS

// log2(10000)/64
#define L2_10K_OVER_64 0.2076205059304602f
// 1/sqrt(128)
#define QSCALE 0.08838834764831845f

// Scratch: sanctioned __device__ globals (no runtime allocation).
__device__ float g_q [NB*NH*NS*DH];
__device__ float g_k [NB*NH*NS*DH];
__device__ float g_v [NB*NH*NS*DH];
__device__ float g_ao[NB*NS*ND];

// ---------------------------------------------------------------------------
// SGEMM: C(4096x2048) = A(4096x2048) @ B(2048x2048), 128x128x16 tiles,
// 256 threads, 8x8 microtile per thread.
// MODE 0: Q proj  -> rope + 1/sqrt(HD) scale, (B,H,S,HD) layout
// MODE 1: K proj  -> rope,                    (B,H,S,HD) layout
// MODE 2: V proj  -> plain,                   (B,H,S,HD) layout
// MODE 3: plain row-major store (output projection)
// ---------------------------------------------------------------------------
template<int MODE>
__global__ void __launch_bounds__(256) gemm_kernel(const float* __restrict__ A,
                                                   const float* __restrict__ B,
                                                   float* __restrict__ C) {
    __shared__ float As[16][132];   // A tile transposed: As[k][m]
    __shared__ float Bs[16][136];   // B tile: Bs[k][n]

    const int tid  = threadIdx.x;
    const int tr   = tid >> 4;      // 0..15 (row group)
    const int tc   = tid & 15;      // 0..15 (col group)
    const int row0 = blockIdx.y * 128;
    const int col0 = blockIdx.x * 128;

    const float* Ab = A + (size_t)row0 * ND;
    const float* Bb = B + col0;

    float acc[8][8];
#pragma unroll
    for (int i = 0; i < 8; ++i)
#pragma unroll
        for (int j = 0; j < 8; ++j) acc[i][j] = 0.f;

    for (int k0 = 0; k0 < ND; k0 += 16) {
        // Load A tile 128x16 (transposed into smem)
#pragma unroll
        for (int it = 0; it < 2; ++it) {
            int idx = tid + it * 256;          // 0..511
            int r   = idx >> 2;                // 0..127
            int c   = (idx & 3) << 2;          // 0,4,8,12
            float4 v = *(const float4*)(Ab + (size_t)r * ND + k0 + c);
            As[c + 0][r] = v.x;
            As[c + 1][r] = v.y;
            As[c + 2][r] = v.z;
            As[c + 3][r] = v.w;
        }
        // Load B tile 16x128
#pragma unroll
        for (int it = 0; it < 2; ++it) {
            int idx = tid + it * 256;
            int kk  = idx >> 5;                // 0..15
            int c   = (idx & 31) << 2;         // 0..124
            *(float4*)&Bs[kk][c] = *(const float4*)(Bb + (size_t)(k0 + kk) * ND + c);
        }
        __syncthreads();

#pragma unroll
        for (int kk = 0; kk < 16; ++kk) {
            float a[8], b[8];
            *(float4*)(a)     = *(const float4*)&As[kk][tr * 8];
            *(float4*)(a + 4) = *(const float4*)&As[kk][tr * 8 + 4];
            *(float4*)(b)     = *(const float4*)&Bs[kk][tc * 8];
            *(float4*)(b + 4) = *(const float4*)&Bs[kk][tc * 8 + 4];
#pragma unroll
            for (int i = 0; i < 8; ++i)
#pragma unroll
                for (int j = 0; j < 8; ++j)
                    acc[i][j] = fmaf(a[i], b[j], acc[i][j]);
        }
        __syncthreads();
    }

    if (MODE == 3) {
#pragma unroll
        for (int i = 0; i < 8; ++i) {
            float* dst = C + (size_t)(row0 + tr * 8 + i) * ND + col0 + tc * 8;
            *(float4*)(dst)     = *(float4*)&acc[i][0];
            *(float4*)(dst + 4) = *(float4*)&acc[i][4];
        }
    } else {
        const int e0    = col0 + tc * 8;     // global output column base
        const int h     = e0 >> 7;           // head (constant per thread)
        const int dbase = e0 & 127;          // head-dim base (even)

        float invf[8];
        if (MODE != 2) {
#pragma unroll
            for (int j = 0; j < 8; ++j) {
                int dm = (dbase + j) & 63;
                invf[j] = exp2f(-(float)dm * L2_10K_OVER_64);
            }
        }

#pragma unroll
        for (int i = 0; i < 8; ++i) {
            int m  = row0 + tr * 8 + i;      // global row = b*S + s
            int bb = m >> 11;
            int ss = m & 2047;
            float* dst = C + (((size_t)(bb * NH + h) * NS + ss) << 7) + dbase;
            if (MODE == 2) {
                *(float4*)(dst)     = *(float4*)&acc[i][0];
                *(float4*)(dst + 4) = *(float4*)&acc[i][4];
            } else {
                float pos = (float)ss;
#pragma unroll
                for (int j = 0; j < 8; j += 2) {
                    float s0, c0, s1, c1;
                    sincosf(pos * invf[j],     &s0, &c0);
                    sincosf(pos * invf[j + 1], &s1, &c1);
                    float v0 = acc[i][j], v1 = acc[i][j + 1];
                    // out_even = x_e*cos(a_e) - x_o*sin(a_e)
                    // out_odd  = x_o*cos(a_o) + x_e*sin(a_o)
                    float o0 = v0 * c0 - v1 * s0;
                    float o1 = v1 * c1 + v0 * s1;
                    if (MODE == 0) { o0 *= QSCALE; o1 *= QSCALE; }
                    dst[j]     = o0;
                    dst[j + 1] = o1;
                }
            }
        }
    }
}

// ---------------------------------------------------------------------------
// Flash attention: 64x64 tiles, online softmax, fp32.
// grid = (S/64, H, B), 256 threads (16x16), thread owns 4 score rows x 4 cols
// and 4 O rows x 8 O cols. Q pre-scaled by 1/sqrt(HD), Q/K pre-roped.
// Output layout (B,S,H,HD) so the final GEMM reads it row-major (4096x2048).
// ---------------------------------------------------------------------------
__global__ void __launch_bounds__(256) flash_kernel(const float* __restrict__ Q,
                                                    const float* __restrict__ K,
                                                    const float* __restrict__ V,
                                                    float* __restrict__ O) {
    extern __shared__ float sm[];
    float* Qst = sm;                   // [128][65] transposed Q tile
    float* Kst = Qst + 128 * 65;       // [128][65] transposed K tile
    float* Vsm = Kst + 128 * 65;       // [64][136] row-major V tile
    float* Ps  = Vsm + 64 * 136;       // [64][65]  probability tile

    const int tid = threadIdx.x;
    const int ty  = tid >> 4;          // 0..15
    const int tx  = tid & 15;          // 0..15
    const int q0  = blockIdx.x * 64;
    const int h   = blockIdx.y;
    const int b   = blockIdx.z;

    const size_t headoff = (size_t)(b * NH + h) * NS * DH;
    const float* Qb = Q + headoff + (size_t)q0 * DH;

    // Load Q tile (transposed, odd pitch -> conflict-free scalar stores)
    for (int idx = tid; idx < 64 * 128; idx += 256) {
        int d = idx & 127, r = idx >> 7;
        Qst[d * 65 + r] = Qb[r * DH + d];
    }

    float o[4][8];
    float mrow[4], lrow[4];
#pragma unroll
    for (int i = 0; i < 4; ++i) {
        mrow[i] = -CUDART_INF_F;
        lrow[i] = 0.f;
#pragma unroll
        for (int j = 0; j < 8; ++j) o[i][j] = 0.f;
    }

    for (int n0 = 0; n0 <= q0; n0 += 64) {
        const float* Kb = K + headoff + (size_t)n0 * DH;
        const float* Vb = V + headoff + (size_t)n0 * DH;
        for (int idx = tid; idx < 64 * 128; idx += 256) {
            int d = idx & 127, r = idx >> 7;
            Kst[d * 65 + r] = Kb[r * DH + d];
        }
        for (int idx = tid; idx < 64 * 32; idx += 256) {
            int r = idx >> 5, c = (idx & 31) << 2;
            *(float4*)&Vsm[r * 136 + c] = *(const float4*)(Vb + r * DH + c);
        }
        __syncthreads();

        // S = Q K^T (Q already scaled)
        float sacc[4][4];
#pragma unroll
        for (int i = 0; i < 4; ++i)
#pragma unroll
            for (int j = 0; j < 4; ++j) sacc[i][j] = 0.f;

#pragma unroll 4
        for (int k = 0; k < 128; ++k) {
            float a[4], bf[4];
#pragma unroll
            for (int i = 0; i < 4; ++i) a[i] = Qst[k * 65 + 4 * ty + i];
#pragma unroll
            for (int j = 0; j < 4; ++j) bf[j] = Kst[k * 65 + 4 * tx + j];
#pragma unroll
            for (int i = 0; i < 4; ++i)
#pragma unroll
                for (int j = 0; j < 4; ++j)
                    sacc[i][j] = fmaf(a[i], bf[j], sacc[i][j]);
        }

        // Causal mask: only the diagonal tile needs it
        if (n0 == q0) {
#pragma unroll
            for (int i = 0; i < 4; ++i)
#pragma unroll
                for (int j = 0; j < 4; ++j)
                    if (4 * tx + j > 4 * ty + i) sacc[i][j] = -CUDART_INF_F;
        }

        // Online softmax per row (16 lanes per row group; xor-shuffles <16
        // stay inside the group)
#pragma unroll
        for (int i = 0; i < 4; ++i) {
            float mt = fmaxf(fmaxf(sacc[i][0], sacc[i][1]),
                             fmaxf(sacc[i][2], sacc[i][3]));
#pragma unroll
            for (int off = 8; off; off >>= 1)
                mt = fmaxf(mt, __shfl_xor_sync(0xffffffffu, mt, off));
            float mn    = fmaxf(mrow[i], mt);
            float alpha = expf(mrow[i] - mn);   // first tile: exp(-inf)=0
            float rs = 0.f;
#pragma unroll
            for (int j = 0; j < 4; ++j) {
                float p = expf(sacc[i][j] - mn);
                Ps[(4 * ty + i) * 65 + 4 * tx + j] = p;
                rs += p;
            }
#pragma unroll
            for (int off = 8; off; off >>= 1)
                rs += __shfl_xor_sync(0xffffffffu, rs, off);
            lrow[i] = lrow[i] * alpha + rs;
            mrow[i] = mn;
#pragma unroll
            for (int j = 0; j < 8; ++j) o[i][j] *= alpha;
        }
        __syncthreads();

        // O += P V
#pragma unroll 2
        for (int k = 0; k < 64; ++k) {
            float vv[8];
            *(float4*)(vv)     = *(float4*)&Vsm[k * 136 + 8 * tx];
            *(float4*)(vv + 4) = *(float4*)&Vsm[k * 136 + 8 * tx + 4];
#pragma unroll
            for (int i = 0; i < 4; ++i) {
                float p = Ps[(4 * ty + i) * 65 + k];
#pragma unroll
                for (int j = 0; j < 8; ++j)
                    o[i][j] = fmaf(p, vv[j], o[i][j]);
            }
        }
        __syncthreads();
    }

    // Normalize and store as (B,S,H,HD)
#pragma unroll
    for (int i = 0; i < 4; ++i) {
        float il = 1.f / lrow[i];
        int s = q0 + 4 * ty + i;
        float* dst = O + ((size_t)(b * NS + s) * NH + h) * DH + 8 * tx;
#pragma unroll
        for (int j = 0; j < 8; ++j) dst[j] = o[i][j] * il;
    }
}

// ---------------------------------------------------------------------------
extern "C" void kernel_launch(void* const* d_in, const int* in_sizes, int n_in,
                              void* d_out, int out_size) {
    const float* x  = (const float*)d_in[0];
    const float* Wq = (const float*)d_in[1];
    const float* Wk = (const float*)d_in[2];
    const float* Wv = (const float*)d_in[3];
    const float* Wo = (const float*)d_in[4];

    float *qp, *kp, *vp, *aop;
    cudaGetSymbolAddress((void**)&qp,  g_q);
    cudaGetSymbolAddress((void**)&kp,  g_k);
    cudaGetSymbolAddress((void**)&vp,  g_v);
    cudaGetSymbolAddress((void**)&aop, g_ao);

    dim3 gg(ND / 128, NM / 128);

    gemm_kernel<0><<<gg, 256>>>(x, Wq, qp);
    gemm_kernel<1><<<gg, 256>>>(x, Wk, kp);
    gemm_kernel<2><<<gg, 256>>>(x, Wv, vp);

    const int smem = (2 * 128 * 65 + 64 * 136 + 64 * 65) * (int)sizeof(float); // 118016 B
    cudaFuncSetAttribute(flash_kernel,
                         cudaFuncAttributeMaxDynamicSharedMemorySize, smem);
    flash_kernel<<<dim3(NS / 64, NH, NB), 256, smem>>>(qp, kp, vp, aop);

    gemm_kernel<3><<<gg, 256>>>(aop, Wo, (float*)d_out);
}

// round 9
// speedup vs baseline: 1.4601x; 1.4601x over previous
#include <cuda_runtime.h>
#include <cuda_bf16.h>
#include <math.h>
#include <math_constants.h>
#include <cstdint>

// Problem constants
#define NB 2
#define NS 2048
#define ND 2048
#define NH 16
#define DH 128
#define NM 4096   // NB*NS

// log2(10000)/64
#define L2_10K_OVER_64 0.2076205059304602f
// 1/sqrt(128)
#define QSCALE 0.08838834764831845f

// Scratch: sanctioned __device__ globals (no runtime allocation).
__device__ float g_q [NB*NH*NS*DH];
__device__ float g_k [NB*NH*NS*DH];
__device__ float g_v [NB*NH*NS*DH];
__device__ float g_ao[NB*NS*ND];
__device__ __nv_bfloat16 g_xh[NM*ND];   // activation hi  (x, later attn-out)
__device__ __nv_bfloat16 g_xl[NM*ND];   // activation lo
__device__ __nv_bfloat16 g_wh[ND*ND];   // transposed weight hi [n][k]
__device__ __nv_bfloat16 g_wl[ND*ND];   // transposed weight lo [n][k]

// ============================ PTX helpers ==================================
__device__ __forceinline__ uint32_t smem_u32(const void* p) {
    uint32_t a;
    asm("{ .reg .u64 t; cvta.to.shared.u64 t, %1; cvt.u32.u64 %0, t; }"
        : "=r"(a) : "l"(p));
    return a;
}

__device__ __forceinline__ void ldsm4(uint32_t* r, uint32_t addr) {
    asm volatile("ldmatrix.sync.aligned.m8n8.x4.shared.b16 {%0,%1,%2,%3}, [%4];"
        : "=r"(r[0]), "=r"(r[1]), "=r"(r[2]), "=r"(r[3]) : "r"(addr));
}

__device__ __forceinline__ void mma_bf16(float* c, const uint32_t* a,
                                         uint32_t b0, uint32_t b1) {
    asm volatile(
        "mma.sync.aligned.m16n8k16.row.col.f32.bf16.bf16.f32 "
        "{%0,%1,%2,%3}, {%4,%5,%6,%7}, {%8,%9}, {%0,%1,%2,%3};"
        : "+f"(c[0]), "+f"(c[1]), "+f"(c[2]), "+f"(c[3])
        : "r"(a[0]), "r"(a[1]), "r"(a[2]), "r"(a[3]), "r"(b0), "r"(b1));
}

__device__ __forceinline__ void cpa16(uint32_t saddr, const void* gaddr) {
    asm volatile("cp.async.cg.shared.global [%0], [%1], 16;"
                 :: "r"(saddr), "l"(gaddr));
}
#define CPA_COMMIT() asm volatile("cp.async.commit_group;")
#define CPA_WAIT1()  asm volatile("cp.async.wait_group 1;")
#define CPA_WAIT0()  asm volatile("cp.async.wait_group 0;")

// =========================== split kernels =================================
// fp32 -> bf16 hi + bf16 lo residual, same layout.
__global__ void __launch_bounds__(256) split_act(const float* __restrict__ in,
                                                 __nv_bfloat16* __restrict__ hi,
                                                 __nv_bfloat16* __restrict__ lo) {
    int i = (blockIdx.x * 256 + threadIdx.x) * 4;
    float4 v = *(const float4*)(in + i);
    __nv_bfloat16 h[4], l[4];
    h[0] = __float2bfloat16_rn(v.x); l[0] = __float2bfloat16_rn(v.x - __bfloat162float(h[0]));
    h[1] = __float2bfloat16_rn(v.y); l[1] = __float2bfloat16_rn(v.y - __bfloat162float(h[1]));
    h[2] = __float2bfloat16_rn(v.z); l[2] = __float2bfloat16_rn(v.z - __bfloat162float(h[2]));
    h[3] = __float2bfloat16_rn(v.w); l[3] = __float2bfloat16_rn(v.w - __bfloat162float(h[3]));
    *(uint2*)(hi + i) = *(uint2*)h;
    *(uint2*)(lo + i) = *(uint2*)l;
}

// W[k][n] fp32 -> Wt hi/lo bf16 [n][k] (transpose + split)
__global__ void __launch_bounds__(256) split_wT(const float* __restrict__ W,
                                                __nv_bfloat16* __restrict__ th,
                                                __nv_bfloat16* __restrict__ tl) {
    __shared__ float t[32][33];
    const int bx = blockIdx.x * 32;   // n tile
    const int by = blockIdx.y * 32;   // k tile
    const int tx = threadIdx.x, ty = threadIdx.y;
#pragma unroll
    for (int j = ty; j < 32; j += 8)
        t[j][tx] = W[(size_t)(by + j) * ND + bx + tx];
    __syncthreads();
#pragma unroll
    for (int j = ty; j < 32; j += 8) {
        float v = t[tx][j];           // = W[by+tx][bx+j]
        __nv_bfloat16 h = __float2bfloat16_rn(v);
        __nv_bfloat16 l = __float2bfloat16_rn(v - __bfloat162float(h));
        th[(size_t)(bx + j) * ND + by + tx] = h;
        tl[(size_t)(bx + j) * ND + by + tx] = l;
    }
}

// ===================== HMMA bf16x3 GEMM (mma.sync) =========================
// C(4096x2048) = A(4096x2048) @ Bt(2048x2048)^T, A/Bt given as bf16 hi/lo.
// CTA 128x128, 8 warps (warp tile 32x64), K_blk=32, cp.async double buffer.
// MODE 0: Q (rope+scale, BHSD)  1: K (rope, BHSD)  2: V (BHSD)  3: plain
#define APITCH 80                          // 32 bf16 + 8 pad -> conflict-free
#define TILE_BYTES (128 * APITCH)          // 10240
#define STAGE_BYTES (4 * TILE_BYTES)       // Ah, Al, Bh, Bl = 40960
#define GSMEM (2 * STAGE_BYTES)            // 81920

template<int MODE>
__global__ void __launch_bounds__(256) gemm_hmma(
    const __nv_bfloat16* __restrict__ Ah, const __nv_bfloat16* __restrict__ Al,
    const __nv_bfloat16* __restrict__ Bh, const __nv_bfloat16* __restrict__ Bl,
    float* __restrict__ C)
{
    extern __shared__ char smc[];
    const uint32_t sbase = smem_u32(smc);
    const int tid  = threadIdx.x;
    const int wid  = tid >> 5;
    const int lane = tid & 31;
    const int wm   = wid & 3;          // M group (32 rows each)
    const int wn   = wid >> 2;         // N group (64 cols each)
    const int row0 = blockIdx.y * 128;
    const int col0 = blockIdx.x * 128;

    // ---- async stage loader: 4 tiles x 128 rows x 4 x 16B chunks ----
    auto load_stage = [&](int buf, int k0) {
#pragma unroll
        for (int t = 0; t < 8; ++t) {
            int id   = tid + t * 256;        // 0..2047
            int tile = id >> 9;
            int rem  = id & 511;
            int r    = rem >> 2;
            int c    = rem & 3;
            uint32_t so = sbase + buf * STAGE_BYTES + tile * TILE_BYTES
                        + r * APITCH + c * 16;
            const __nv_bfloat16* g;
            if      (tile == 0) g = Ah + (size_t)(row0 + r) * ND + k0 + c * 8;
            else if (tile == 1) g = Al + (size_t)(row0 + r) * ND + k0 + c * 8;
            else if (tile == 2) g = Bh + (size_t)(col0 + r) * ND + k0 + c * 8;
            else                g = Bl + (size_t)(col0 + r) * ND + k0 + c * 8;
            cpa16(so, g);
        }
        CPA_COMMIT();
    };

    float acc[2][8][4];
#pragma unroll
    for (int mf = 0; mf < 2; ++mf)
#pragma unroll
        for (int nf = 0; nf < 8; ++nf)
#pragma unroll
            for (int e = 0; e < 4; ++e) acc[mf][nf][e] = 0.f;

    load_stage(0, 0);

    for (int it = 0; it < 64; ++it) {
        const int buf = it & 1;
        if (it + 1 < 64) { load_stage(buf ^ 1, (it + 1) * 32); CPA_WAIT1(); }
        else             { CPA_WAIT0(); }
        __syncthreads();

        const uint32_t sA  = sbase + buf * STAGE_BYTES;
        const uint32_t sAl = sA + TILE_BYTES;
        const uint32_t sB  = sA + 2 * TILE_BYTES;
        const uint32_t sBl = sA + 3 * TILE_BYTES;

#pragma unroll
        for (int ks = 0; ks < 2; ++ks) {
            const int akb = ks * 32 + (lane >> 4) * 16;
            uint32_t ah[2][4], al[2][4];
#pragma unroll
            for (int mf = 0; mf < 2; ++mf) {
                uint32_t ro = (wm * 32 + mf * 16 + (lane & 15)) * APITCH + akb;
                ldsm4(ah[mf], sA  + ro);
                ldsm4(al[mf], sAl + ro);
            }
            const int brow = wn * 64 + (lane & 7) + ((lane >> 4) << 3);
            const int bkb  = ks * 32 + ((lane >> 3) & 1) * 16;
#pragma unroll
            for (int nf2 = 0; nf2 < 4; ++nf2) {
                uint32_t bo = (brow + nf2 * 16) * APITCH + bkb;
                uint32_t bh[4], bl[4];
                ldsm4(bh, sB  + bo);
                ldsm4(bl, sBl + bo);
#pragma unroll
                for (int half = 0; half < 2; ++half) {
                    uint32_t h0 = bh[half * 2], h1 = bh[half * 2 + 1];
                    uint32_t l0 = bl[half * 2], l1 = bl[half * 2 + 1];
                    int nf = nf2 * 2 + half;
#pragma unroll
                    for (int mf = 0; mf < 2; ++mf) {
                        mma_bf16(acc[mf][nf], ah[mf], h0, h1);
                        mma_bf16(acc[mf][nf], ah[mf], l0, l1);
                        mma_bf16(acc[mf][nf], al[mf], h0, h1);
                    }
                }
            }
        }
        __syncthreads();   // all warps done reading buf before it is refilled
    }

    // ---- epilogue: c-frag rows = lane/4 (+8), cols = 2*(lane%4)+{0,1} ----
#pragma unroll
    for (int mf = 0; mf < 2; ++mf) {
        const int mrow = row0 + wm * 32 + mf * 16 + (lane >> 2);
#pragma unroll
        for (int rr = 0; rr < 2; ++rr) {           // rr=0 -> c0/c1, rr=1 -> c2/c3
            const int m  = mrow + rr * 8;
            const int bb = m >> 11, ss = m & 2047;
#pragma unroll
            for (int nf = 0; nf < 8; ++nf) {
                const int cloc = wn * 64 + nf * 8 + ((lane & 3) << 1); // 0..127
                const int col  = col0 + cloc;
                float v0 = acc[mf][nf][rr * 2 + 0];
                float v1 = acc[mf][nf][rr * 2 + 1];
                if (MODE == 3) {
                    *(float2*)(C + (size_t)m * ND + col) = make_float2(v0, v1);
                } else {
                    const int h = col >> 7;
                    const int d = cloc & 127;
                    float* dst = C + (((size_t)(bb * NH + h) * NS + ss) << 7) + d;
                    if (MODE == 2) {
                        *(float2*)dst = make_float2(v0, v1);
                    } else {
                        float pos  = (float)ss;
                        float inv0 = exp2f(-(float)( d      & 63) * L2_10K_OVER_64);
                        float inv1 = exp2f(-(float)((d + 1) & 63) * L2_10K_OVER_64);
                        float s0, c0, s1, c1;
                        sincosf(pos * inv0, &s0, &c0);
                        sincosf(pos * inv1, &s1, &c1);
                        float o0 = v0 * c0 - v1 * s0;
                        float o1 = v1 * c1 + v0 * s1;
                        if (MODE == 0) { o0 *= QSCALE; o1 *= QSCALE; }
                        *(float2*)dst = make_float2(o0, o1);
                    }
                }
            }
        }
    }
}

// ---------------------------------------------------------------------------
// Flash attention: unchanged from round 4 (known-good).
// ---------------------------------------------------------------------------
__global__ void __launch_bounds__(256) flash_kernel(const float* __restrict__ Q,
                                                    const float* __restrict__ K,
                                                    const float* __restrict__ V,
                                                    float* __restrict__ O) {
    extern __shared__ float sm[];
    float* Qst = sm;                   // [128][65] transposed Q tile
    float* Kst = Qst + 128 * 65;       // [128][65] transposed K tile
    float* Vsm = Kst + 128 * 65;       // [64][136] row-major V tile
    float* Ps  = Vsm + 64 * 136;       // [64][65]  probability tile

    const int tid = threadIdx.x;
    const int ty  = tid >> 4;
    const int tx  = tid & 15;
    const int q0  = blockIdx.x * 64;
    const int h   = blockIdx.y;
    const int b   = blockIdx.z;

    const size_t headoff = (size_t)(b * NH + h) * NS * DH;
    const float* Qb = Q + headoff + (size_t)q0 * DH;

    for (int idx = tid; idx < 64 * 128; idx += 256) {
        int d = idx & 127, r = idx >> 7;
        Qst[d * 65 + r] = Qb[r * DH + d];
    }

    float o[4][8];
    float mrow[4], lrow[4];
#pragma unroll
    for (int i = 0; i < 4; ++i) {
        mrow[i] = -CUDART_INF_F;
        lrow[i] = 0.f;
#pragma unroll
        for (int j = 0; j < 8; ++j) o[i][j] = 0.f;
    }

    for (int n0 = 0; n0 <= q0; n0 += 64) {
        const float* Kb = K + headoff + (size_t)n0 * DH;
        const float* Vb = V + headoff + (size_t)n0 * DH;
        for (int idx = tid; idx < 64 * 128; idx += 256) {
            int d = idx & 127, r = idx >> 7;
            Kst[d * 65 + r] = Kb[r * DH + d];
        }
        for (int idx = tid; idx < 64 * 32; idx += 256) {
            int r = idx >> 5, c = (idx & 31) << 2;
            *(float4*)&Vsm[r * 136 + c] = *(const float4*)(Vb + r * DH + c);
        }
        __syncthreads();

        float sacc[4][4];
#pragma unroll
        for (int i = 0; i < 4; ++i)
#pragma unroll
            for (int j = 0; j < 4; ++j) sacc[i][j] = 0.f;

#pragma unroll 4
        for (int k = 0; k < 128; ++k) {
            float a[4], bf[4];
#pragma unroll
            for (int i = 0; i < 4; ++i) a[i] = Qst[k * 65 + 4 * ty + i];
#pragma unroll
            for (int j = 0; j < 4; ++j) bf[j] = Kst[k * 65 + 4 * tx + j];
#pragma unroll
            for (int i = 0; i < 4; ++i)
#pragma unroll
                for (int j = 0; j < 4; ++j)
                    sacc[i][j] = fmaf(a[i], bf[j], sacc[i][j]);
        }

        if (n0 == q0) {
#pragma unroll
            for (int i = 0; i < 4; ++i)
#pragma unroll
                for (int j = 0; j < 4; ++j)
                    if (4 * tx + j > 4 * ty + i) sacc[i][j] = -CUDART_INF_F;
        }

#pragma unroll
        for (int i = 0; i < 4; ++i) {
            float mt = fmaxf(fmaxf(sacc[i][0], sacc[i][1]),
                             fmaxf(sacc[i][2], sacc[i][3]));
#pragma unroll
            for (int off = 8; off; off >>= 1)
                mt = fmaxf(mt, __shfl_xor_sync(0xffffffffu, mt, off));
            float mn    = fmaxf(mrow[i], mt);
            float alpha = expf(mrow[i] - mn);
            float rs = 0.f;
#pragma unroll
            for (int j = 0; j < 4; ++j) {
                float p = expf(sacc[i][j] - mn);
                Ps[(4 * ty + i) * 65 + 4 * tx + j] = p;
                rs += p;
            }
#pragma unroll
            for (int off = 8; off; off >>= 1)
                rs += __shfl_xor_sync(0xffffffffu, rs, off);
            lrow[i] = lrow[i] * alpha + rs;
            mrow[i] = mn;
#pragma unroll
            for (int j = 0; j < 8; ++j) o[i][j] *= alpha;
        }
        __syncthreads();

#pragma unroll 2
        for (int k = 0; k < 64; ++k) {
            float vv[8];
            *(float4*)(vv)     = *(float4*)&Vsm[k * 136 + 8 * tx];
            *(float4*)(vv + 4) = *(float4*)&Vsm[k * 136 + 8 * tx + 4];
#pragma unroll
            for (int i = 0; i < 4; ++i) {
                float p = Ps[(4 * ty + i) * 65 + k];
#pragma unroll
                for (int j = 0; j < 8; ++j)
                    o[i][j] = fmaf(p, vv[j], o[i][j]);
            }
        }
        __syncthreads();
    }

#pragma unroll
    for (int i = 0; i < 4; ++i) {
        float il = 1.f / lrow[i];
        int s = q0 + 4 * ty + i;
        float* dst = O + ((size_t)(b * NS + s) * NH + h) * DH + 8 * tx;
#pragma unroll
        for (int j = 0; j < 8; ++j) dst[j] = o[i][j] * il;
    }
}

// ---------------------------------------------------------------------------
extern "C" void kernel_launch(void* const* d_in, const int* in_sizes, int n_in,
                              void* d_out, int out_size) {
    const float* x  = (const float*)d_in[0];
    const float* Wq = (const float*)d_in[1];
    const float* Wk = (const float*)d_in[2];
    const float* Wv = (const float*)d_in[3];
    const float* Wo = (const float*)d_in[4];

    float *qp, *kp, *vp, *aop;
    __nv_bfloat16 *xh, *xl, *wh, *wl;
    cudaGetSymbolAddress((void**)&qp,  g_q);
    cudaGetSymbolAddress((void**)&kp,  g_k);
    cudaGetSymbolAddress((void**)&vp,  g_v);
    cudaGetSymbolAddress((void**)&aop, g_ao);
    cudaGetSymbolAddress((void**)&xh,  g_xh);
    cudaGetSymbolAddress((void**)&xl,  g_xl);
    cudaGetSymbolAddress((void**)&wh,  g_wh);
    cudaGetSymbolAddress((void**)&wl,  g_wl);

    cudaFuncSetAttribute(gemm_hmma<0>, cudaFuncAttributeMaxDynamicSharedMemorySize, GSMEM);
    cudaFuncSetAttribute(gemm_hmma<1>, cudaFuncAttributeMaxDynamicSharedMemorySize, GSMEM);
    cudaFuncSetAttribute(gemm_hmma<2>, cudaFuncAttributeMaxDynamicSharedMemorySize, GSMEM);
    cudaFuncSetAttribute(gemm_hmma<3>, cudaFuncAttributeMaxDynamicSharedMemorySize, GSMEM);

    dim3 gg(ND / 128, NM / 128);          // 16 x 32 CTAs
    dim3 tg(ND / 32, ND / 32);            // transpose/split grid
    dim3 tb(32, 8);
    const int actblocks = NM * ND / (256 * 4);  // 8192

    // x -> bf16 hi/lo (shared by Q,K,V projections)
    split_act<<<actblocks, 256>>>(x, xh, xl);

    // Stream order serializes each weight split with its consumer GEMM.
    split_wT<<<tg, tb>>>(Wq, wh, wl);
    gemm_hmma<0><<<gg, 256, GSMEM>>>(xh, xl, wh, wl, qp);
    split_wT<<<tg, tb>>>(Wk, wh, wl);
    gemm_hmma<1><<<gg, 256, GSMEM>>>(xh, xl, wh, wl, kp);
    split_wT<<<tg, tb>>>(Wv, wh, wl);
    gemm_hmma<2><<<gg, 256, GSMEM>>>(xh, xl, wh, wl, vp);

    const int fsmem = (2 * 128 * 65 + 64 * 136 + 64 * 65) * (int)sizeof(float); // 118016
    cudaFuncSetAttribute(flash_kernel,
                         cudaFuncAttributeMaxDynamicSharedMemorySize, fsmem);
    flash_kernel<<<dim3(NS / 64, NH, NB), 256, fsmem>>>(qp, kp, vp, aop);

    // attn-out -> bf16 hi/lo (reuses x buffers; x no longer needed)
    split_act<<<actblocks, 256>>>(aop, xh, xl);
    split_wT<<<tg, tb>>>(Wo, wh, wl);
    gemm_hmma<3><<<gg, 256, GSMEM>>>(xh, xl, wh, wl, (float*)d_out);
}

// round 10
// speedup vs baseline: 2.8623x; 1.9604x over previous
#include <cuda_runtime.h>
#include <cuda_bf16.h>
#include <math.h>
#include <math_constants.h>
#include <cstdint>

// Problem constants
#define NB 2
#define NS 2048
#define ND 2048
#define NH 16
#define DH 128
#define NM 4096   // NB*NS

#define L2_10K_OVER_64 0.2076205059304602f   // log2(10000)/64
#define QSCALE 0.08838834764831845f          // 1/sqrt(128)

// Scratch: sanctioned __device__ globals (no runtime allocation).
__device__ __nv_bfloat16 g_xh [NM*ND];         // activation hi (x, then attn-out)
__device__ __nv_bfloat16 g_xl [NM*ND];         // activation lo
__device__ __nv_bfloat16 g_wh [ND*ND];         // transposed weight hi [n][k]
__device__ __nv_bfloat16 g_wl [ND*ND];         // transposed weight lo [n][k]
__device__ __nv_bfloat16 g_qh [NB*NH*NS*DH];   // Q hi  (B,H,S,D), roped+scaled
__device__ __nv_bfloat16 g_ql [NB*NH*NS*DH];
__device__ __nv_bfloat16 g_kh [NB*NH*NS*DH];   // K hi  (B,H,S,D), roped
__device__ __nv_bfloat16 g_kl [NB*NH*NS*DH];
__device__ __nv_bfloat16 g_vth[NB*NH*DH*NS];   // V^T hi (B,H,D,S)
__device__ __nv_bfloat16 g_vtl[NB*NH*DH*NS];

// ============================ PTX helpers ==================================
__device__ __forceinline__ uint32_t smem_u32(const void* p) {
    uint32_t a;
    asm("{ .reg .u64 t; cvta.to.shared.u64 t, %1; cvt.u32.u64 %0, t; }"
        : "=r"(a) : "l"(p));
    return a;
}

__device__ __forceinline__ void ldsm4(uint32_t* r, uint32_t addr) {
    asm volatile("ldmatrix.sync.aligned.m8n8.x4.shared.b16 {%0,%1,%2,%3}, [%4];"
        : "=r"(r[0]), "=r"(r[1]), "=r"(r[2]), "=r"(r[3]) : "r"(addr));
}

__device__ __forceinline__ void mma_bf16(float* c, const uint32_t* a,
                                         uint32_t b0, uint32_t b1) {
    asm volatile(
        "mma.sync.aligned.m16n8k16.row.col.f32.bf16.bf16.f32 "
        "{%0,%1,%2,%3}, {%4,%5,%6,%7}, {%8,%9}, {%0,%1,%2,%3};"
        : "+f"(c[0]), "+f"(c[1]), "+f"(c[2]), "+f"(c[3])
        : "r"(a[0]), "r"(a[1]), "r"(a[2]), "r"(a[3]), "r"(b0), "r"(b1));
}

__device__ __forceinline__ void cpa16(uint32_t saddr, const void* gaddr) {
    asm volatile("cp.async.cg.shared.global [%0], [%1], 16;"
                 :: "r"(saddr), "l"(gaddr));
}
#define CPA_COMMIT() asm volatile("cp.async.commit_group;")
#define CPA_WAIT1()  asm volatile("cp.async.wait_group 1;")
#define CPA_WAIT0()  asm volatile("cp.async.wait_group 0;")

// pack (a,b) into bf16x2 hi word + bf16x2 lo-residual word
__device__ __forceinline__ void hilo2(float a, float b, uint32_t& hi, uint32_t& lo) {
    __nv_bfloat16 ha = __float2bfloat16_rn(a);
    __nv_bfloat16 hb = __float2bfloat16_rn(b);
    __nv_bfloat162 hp(ha, hb);
    __nv_bfloat162 lp = __floats2bfloat162_rn(a - __bfloat162float(ha),
                                              b - __bfloat162float(hb));
    hi = *reinterpret_cast<uint32_t*>(&hp);
    lo = *reinterpret_cast<uint32_t*>(&lp);
}

// =========================== split kernels =================================
__global__ void __launch_bounds__(256) split_act(const float* __restrict__ in,
                                                 __nv_bfloat16* __restrict__ hi,
                                                 __nv_bfloat16* __restrict__ lo) {
    int i = (blockIdx.x * 256 + threadIdx.x) * 4;
    float4 v = *(const float4*)(in + i);
    uint32_t h0, l0, h1, l1;
    hilo2(v.x, v.y, h0, l0);
    hilo2(v.z, v.w, h1, l1);
    *(uint2*)(hi + i) = make_uint2(h0, h1);
    *(uint2*)(lo + i) = make_uint2(l0, l1);
}

// W[k][n] fp32 -> Wt hi/lo bf16 [n][k] (transpose + split)
__global__ void __launch_bounds__(256) split_wT(const float* __restrict__ W,
                                                __nv_bfloat16* __restrict__ th,
                                                __nv_bfloat16* __restrict__ tl) {
    __shared__ float t[32][33];
    const int bx = blockIdx.x * 32;   // n tile
    const int by = blockIdx.y * 32;   // k tile
    const int tx = threadIdx.x, ty = threadIdx.y;
#pragma unroll
    for (int j = ty; j < 32; j += 8)
        t[j][tx] = W[(size_t)(by + j) * ND + bx + tx];
    __syncthreads();
#pragma unroll
    for (int j = ty; j < 32; j += 8) {
        float v = t[tx][j];           // = W[by+tx][bx+j]
        __nv_bfloat16 h = __float2bfloat16_rn(v);
        __nv_bfloat16 l = __float2bfloat16_rn(v - __bfloat162float(h));
        th[(size_t)(bx + j) * ND + by + tx] = h;
        tl[(size_t)(bx + j) * ND + by + tx] = l;
    }
}

// ===================== HMMA bf16x3 GEMM (mma.sync) =========================
// C = A @ Bt^T; CTA 128x128, 8 warps, K_blk=32, cp.async double buffer.
// MODE 0: Q -> rope+scale -> bf16 hi/lo (B,H,S,D)
// MODE 1: K -> rope       -> bf16 hi/lo (B,H,S,D)
// MODE 2: V -> bf16 hi/lo transposed (B,H,D,S)
// MODE 3: plain fp32 row-major (final projection)
#define APITCH 80
#define TILE_BYTES (128 * APITCH)
#define STAGE_BYTES (4 * TILE_BYTES)
#define GSMEM (2 * STAGE_BYTES)            // 81920

template<int MODE>
__global__ void __launch_bounds__(256) gemm_hmma(
    const __nv_bfloat16* __restrict__ Ah, const __nv_bfloat16* __restrict__ Al,
    const __nv_bfloat16* __restrict__ Bh, const __nv_bfloat16* __restrict__ Bl,
    float* __restrict__ C,
    __nv_bfloat16* __restrict__ Ch, __nv_bfloat16* __restrict__ Cl)
{
    extern __shared__ char smc[];
    const uint32_t sbase = smem_u32(smc);
    const int tid  = threadIdx.x;
    const int wid  = tid >> 5;
    const int lane = tid & 31;
    const int wm   = wid & 3;
    const int wn   = wid >> 2;
    const int row0 = blockIdx.y * 128;
    const int col0 = blockIdx.x * 128;

    auto load_stage = [&](int buf, int k0) {
#pragma unroll
        for (int t = 0; t < 8; ++t) {
            int id   = tid + t * 256;
            int tile = id >> 9;
            int rem  = id & 511;
            int r    = rem >> 2;
            int c    = rem & 3;
            uint32_t so = sbase + buf * STAGE_BYTES + tile * TILE_BYTES
                        + r * APITCH + c * 16;
            const __nv_bfloat16* g;
            if      (tile == 0) g = Ah + (size_t)(row0 + r) * ND + k0 + c * 8;
            else if (tile == 1) g = Al + (size_t)(row0 + r) * ND + k0 + c * 8;
            else if (tile == 2) g = Bh + (size_t)(col0 + r) * ND + k0 + c * 8;
            else                g = Bl + (size_t)(col0 + r) * ND + k0 + c * 8;
            cpa16(so, g);
        }
        CPA_COMMIT();
    };

    float acc[2][8][4];
#pragma unroll
    for (int mf = 0; mf < 2; ++mf)
#pragma unroll
        for (int nf = 0; nf < 8; ++nf)
#pragma unroll
            for (int e = 0; e < 4; ++e) acc[mf][nf][e] = 0.f;

    load_stage(0, 0);

    for (int it = 0; it < 64; ++it) {
        const int buf = it & 1;
        if (it + 1 < 64) { load_stage(buf ^ 1, (it + 1) * 32); CPA_WAIT1(); }
        else             { CPA_WAIT0(); }
        __syncthreads();

        const uint32_t sA  = sbase + buf * STAGE_BYTES;
        const uint32_t sAl = sA + TILE_BYTES;
        const uint32_t sB  = sA + 2 * TILE_BYTES;
        const uint32_t sBl = sA + 3 * TILE_BYTES;

#pragma unroll
        for (int ks = 0; ks < 2; ++ks) {
            const int akb = ks * 32 + (lane >> 4) * 16;
            uint32_t ah[2][4], al[2][4];
#pragma unroll
            for (int mf = 0; mf < 2; ++mf) {
                uint32_t ro = (wm * 32 + mf * 16 + (lane & 15)) * APITCH + akb;
                ldsm4(ah[mf], sA  + ro);
                ldsm4(al[mf], sAl + ro);
            }
            const int brow = wn * 64 + (lane & 7) + ((lane >> 4) << 3);
            const int bkb  = ks * 32 + ((lane >> 3) & 1) * 16;
#pragma unroll
            for (int nf2 = 0; nf2 < 4; ++nf2) {
                uint32_t bo = (brow + nf2 * 16) * APITCH + bkb;
                uint32_t bh[4], bl[4];
                ldsm4(bh, sB  + bo);
                ldsm4(bl, sBl + bo);
#pragma unroll
                for (int half = 0; half < 2; ++half) {
                    uint32_t h0 = bh[half * 2], h1 = bh[half * 2 + 1];
                    uint32_t l0 = bl[half * 2], l1 = bl[half * 2 + 1];
                    int nf = nf2 * 2 + half;
#pragma unroll
                    for (int mf = 0; mf < 2; ++mf) {
                        mma_bf16(acc[mf][nf], ah[mf], h0, h1);
                        mma_bf16(acc[mf][nf], ah[mf], l0, l1);
                        mma_bf16(acc[mf][nf], al[mf], h0, h1);
                    }
                }
            }
        }
        __syncthreads();
    }

#pragma unroll
    for (int mf = 0; mf < 2; ++mf) {
        const int mrow = row0 + wm * 32 + mf * 16 + (lane >> 2);
#pragma unroll
        for (int rr = 0; rr < 2; ++rr) {
            const int m  = mrow + rr * 8;
            const int bb = m >> 11, ss = m & 2047;
#pragma unroll
            for (int nf = 0; nf < 8; ++nf) {
                const int cloc = wn * 64 + nf * 8 + ((lane & 3) << 1);
                const int col  = col0 + cloc;
                float v0 = acc[mf][nf][rr * 2 + 0];
                float v1 = acc[mf][nf][rr * 2 + 1];
                if (MODE == 3) {
                    *(float2*)(C + (size_t)m * ND + col) = make_float2(v0, v1);
                } else if (MODE == 2) {
                    const int h = col >> 7;
                    const int d = cloc & 127;
                    size_t vb = ((size_t)(bb * NH + h) * DH + d) * NS + ss;
                    __nv_bfloat16 h0 = __float2bfloat16_rn(v0);
                    __nv_bfloat16 h1 = __float2bfloat16_rn(v1);
                    Ch[vb]      = h0;
                    Ch[vb + NS] = h1;
                    Cl[vb]      = __float2bfloat16_rn(v0 - __bfloat162float(h0));
                    Cl[vb + NS] = __float2bfloat16_rn(v1 - __bfloat162float(h1));
                } else {
                    const int h = col >> 7;
                    const int d = cloc & 127;
                    size_t  ob = (((size_t)(bb * NH + h) * NS + ss) << 7) + d;
                    float pos  = (float)ss;
                    float inv0 = exp2f(-(float)( d      & 63) * L2_10K_OVER_64);
                    float inv1 = exp2f(-(float)((d + 1) & 63) * L2_10K_OVER_64);
                    float s0, c0, s1, c1;
                    sincosf(pos * inv0, &s0, &c0);
                    sincosf(pos * inv1, &s1, &c1);
                    float o0 = v0 * c0 - v1 * s0;
                    float o1 = v1 * c1 + v0 * s1;
                    if (MODE == 0) { o0 *= QSCALE; o1 *= QSCALE; }
                    uint32_t hp, lp;
                    hilo2(o0, o1, hp, lp);
                    *reinterpret_cast<uint32_t*>(Ch + ob) = hp;
                    *reinterpret_cast<uint32_t*>(Cl + ob) = lp;
                }
            }
        }
    }
}

// ======================= flash attention (mma.sync) ========================
// CTA: 128 q-rows, 8 warps (warp = m16 x n64 x d128), k-tile 64.
// Q/K/V pre-split bf16 hi/lo; V pre-transposed (B,H,D,S).
// Output: bf16 hi/lo into (B,S,H*D) buffers (final GEMM input).
#define QPB 272                       // 128 bf16 + 8 pad (bytes)
#define VPB 144                       // 64 bf16 + 8 pad (bytes)
#define OQH 0
#define OQL (OQH + 128*QPB)
#define OKH (OQL + 128*QPB)
#define OKL (OKH + 2*64*QPB)
#define OVH (OKL + 2*64*QPB)
#define OVL (OVH + 2*128*VPB)
#define FSMEM (OVL + 2*128*VPB)       // 212992

__global__ void __launch_bounds__(256, 1) flash_mma(
    const __nv_bfloat16* __restrict__ Qh, const __nv_bfloat16* __restrict__ Ql,
    const __nv_bfloat16* __restrict__ Kh, const __nv_bfloat16* __restrict__ Kl,
    const __nv_bfloat16* __restrict__ Vth, const __nv_bfloat16* __restrict__ Vtl,
    __nv_bfloat16* __restrict__ Oh, __nv_bfloat16* __restrict__ Ol)
{
    extern __shared__ char smc[];
    const uint32_t sb = smem_u32(smc);
    const int tid = threadIdx.x, wid = tid >> 5, lane = tid & 31;
    const int qt = gridDim.x - 1 - blockIdx.x;     // heavy tiles first
    const int q0 = qt * 128;
    const int h  = blockIdx.y, b = blockIdx.z;
    const size_t ho = (size_t)(b * NH + h) * NS * DH;

    // Q tile (loaded once)
#pragma unroll
    for (int t = 0; t < 16; ++t) {
        int id  = tid + t * 256;           // 0..4095
        int arr = id >> 11;
        int rem = id & 2047;
        int r = rem >> 4, c = rem & 15;
        uint32_t so = sb + (arr ? OQL : OQH) + r * QPB + c * 16;
        const __nv_bfloat16* g = (arr ? Ql : Qh) + ho + (size_t)(q0 + r) * DH + c * 8;
        cpa16(so, g);
    }

    auto loadKV = [&](int buf, int n0) {
#pragma unroll
        for (int t = 0; t < 8; ++t) {      // K: 64 rows x 16 chunks x 2
            int id  = tid + t * 256;
            int arr = id >> 10;
            int rem = id & 1023;
            int r = rem >> 4, c = rem & 15;
            uint32_t so = sb + (arr ? OKL : OKH) + buf * (64 * QPB) + r * QPB + c * 16;
            const __nv_bfloat16* g = (arr ? Kl : Kh) + ho + (size_t)(n0 + r) * DH + c * 8;
            cpa16(so, g);
        }
#pragma unroll
        for (int t = 0; t < 8; ++t) {      // Vt: 128 rows x 8 chunks x 2
            int id  = tid + t * 256;
            int arr = id >> 10;
            int rem = id & 1023;
            int r = rem >> 3, c = rem & 7;
            uint32_t so = sb + (arr ? OVL : OVH) + buf * (128 * VPB) + r * VPB + c * 16;
            const __nv_bfloat16* g = (arr ? Vtl : Vth) + ho + (size_t)r * NS + n0 + c * 8;
            cpa16(so, g);
        }
    };

    loadKV(0, 0);
    CPA_COMMIT();                           // group: Q + KV0

    const int rmin = q0 + wid * 16;
    float o[16][4];
#pragma unroll
    for (int nf = 0; nf < 16; ++nf)
#pragma unroll
        for (int e = 0; e < 4; ++e) o[nf][e] = 0.f;
    float m0 = -CUDART_INF_F, m1 = -CUDART_INF_F, l0 = 0.f, l1 = 0.f;

    const uint32_t a_off  = (uint32_t)((wid * 16 + (lane & 15)) * QPB + (lane >> 4) * 16);
    const uint32_t b_row  = (uint32_t)((lane & 7) + ((lane >> 4) << 3));
    const uint32_t b_koff = (uint32_t)(((lane >> 3) & 1) * 16);

    const int niter = q0 / 64 + 2;
    for (int it = 0; it < niter; ++it) {
        const int n0 = it * 64, buf = it & 1;
        if (it + 1 < niter) { loadKV(buf ^ 1, (it + 1) * 64); CPA_COMMIT(); CPA_WAIT1(); }
        else                { CPA_WAIT0(); }
        __syncthreads();

        if (n0 <= rmin + 15) {              // tile not fully above diagonal
            // ---- S = Q K^T (3-product split) ----
            float sc[8][4];
#pragma unroll
            for (int nf = 0; nf < 8; ++nf)
#pragma unroll
                for (int e = 0; e < 4; ++e) sc[nf][e] = 0.f;

            const uint32_t kh_b = sb + OKH + buf * (64 * QPB) + b_row * QPB + b_koff;
            const uint32_t kl_b = sb + OKL + buf * (64 * QPB) + b_row * QPB + b_koff;
#pragma unroll
            for (int t = 0; t < 8; ++t) {
                uint32_t ah[4], av[4];
                ldsm4(ah, sb + OQH + a_off + t * 32);
                ldsm4(av, sb + OQL + a_off + t * 32);
#pragma unroll
                for (int nf2 = 0; nf2 < 4; ++nf2) {
                    uint32_t bh[4], bl[4];
                    ldsm4(bh, kh_b + nf2 * (16 * QPB) + t * 32);
                    ldsm4(bl, kl_b + nf2 * (16 * QPB) + t * 32);
                    mma_bf16(sc[2*nf2],   ah, bh[0], bh[1]);
                    mma_bf16(sc[2*nf2],   ah, bl[0], bl[1]);
                    mma_bf16(sc[2*nf2],   av, bh[0], bh[1]);
                    mma_bf16(sc[2*nf2+1], ah, bh[2], bh[3]);
                    mma_bf16(sc[2*nf2+1], ah, bl[2], bl[3]);
                    mma_bf16(sc[2*nf2+1], av, bh[2], bh[3]);
                }
            }

            // ---- causal mask (partial tiles only) ----
            const int r_lo = rmin + (lane >> 2);
            if (n0 + 63 > rmin) {
#pragma unroll
                for (int nf = 0; nf < 8; ++nf) {
                    int cbase = n0 + nf * 8 + ((lane & 3) << 1);
#pragma unroll
                    for (int e = 0; e < 4; ++e) {
                        int col = cbase + (e & 1);
                        int row = r_lo + ((e >> 1) << 3);
                        if (col > row) sc[nf][e] = -CUDART_INF_F;
                    }
                }
            }

            // ---- online softmax ----
            float mx0 = -CUDART_INF_F, mx1 = -CUDART_INF_F;
#pragma unroll
            for (int nf = 0; nf < 8; ++nf) {
                mx0 = fmaxf(mx0, fmaxf(sc[nf][0], sc[nf][1]));
                mx1 = fmaxf(mx1, fmaxf(sc[nf][2], sc[nf][3]));
            }
            mx0 = fmaxf(mx0, __shfl_xor_sync(0xffffffffu, mx0, 1));
            mx0 = fmaxf(mx0, __shfl_xor_sync(0xffffffffu, mx0, 2));
            mx1 = fmaxf(mx1, __shfl_xor_sync(0xffffffffu, mx1, 1));
            mx1 = fmaxf(mx1, __shfl_xor_sync(0xffffffffu, mx1, 2));
            float mn0 = fmaxf(m0, mx0), mn1 = fmaxf(m1, mx1);
            float al0 = __expf(m0 - mn0), al1 = __expf(m1 - mn1);
            float rs0 = 0.f, rs1 = 0.f;
#pragma unroll
            for (int nf = 0; nf < 8; ++nf) {
                sc[nf][0] = __expf(sc[nf][0] - mn0);
                sc[nf][1] = __expf(sc[nf][1] - mn0);
                sc[nf][2] = __expf(sc[nf][2] - mn1);
                sc[nf][3] = __expf(sc[nf][3] - mn1);
                rs0 += sc[nf][0] + sc[nf][1];
                rs1 += sc[nf][2] + sc[nf][3];
            }
            rs0 += __shfl_xor_sync(0xffffffffu, rs0, 1);
            rs0 += __shfl_xor_sync(0xffffffffu, rs0, 2);
            rs1 += __shfl_xor_sync(0xffffffffu, rs1, 1);
            rs1 += __shfl_xor_sync(0xffffffffu, rs1, 2);
            l0 = l0 * al0 + rs0;  l1 = l1 * al1 + rs1;
            m0 = mn0;             m1 = mn1;
#pragma unroll
            for (int nf = 0; nf < 16; ++nf) {
                o[nf][0] *= al0; o[nf][1] *= al0;
                o[nf][2] *= al1; o[nf][3] *= al1;
            }

            // ---- O += P V (P split in-register; acc frags == A frags) ----
            const uint32_t vh_b = sb + OVH + buf * (128 * VPB) + b_row * VPB + b_koff;
            const uint32_t vl_b = sb + OVL + buf * (128 * VPB) + b_row * VPB + b_koff;
#pragma unroll
            for (int t = 0; t < 4; ++t) {
                uint32_t pah[4], pal[4];
                hilo2(sc[2*t][0],   sc[2*t][1],   pah[0], pal[0]);
                hilo2(sc[2*t][2],   sc[2*t][3],   pah[1], pal[1]);
                hilo2(sc[2*t+1][0], sc[2*t+1][1], pah[2], pal[2]);
                hilo2(sc[2*t+1][2], sc[2*t+1][3], pah[3], pal[3]);
#pragma unroll
                for (int nd2 = 0; nd2 < 8; ++nd2) {
                    uint32_t vh[4], vl[4];
                    ldsm4(vh, vh_b + nd2 * (16 * VPB) + t * 32);
                    ldsm4(vl, vl_b + nd2 * (16 * VPB) + t * 32);
                    mma_bf16(o[2*nd2],   pah, vh[0], vh[1]);
                    mma_bf16(o[2*nd2],   pah, vl[0], vl[1]);
                    mma_bf16(o[2*nd2],   pal, vh[0], vh[1]);
                    mma_bf16(o[2*nd2+1], pah, vh[2], vh[3]);
                    mma_bf16(o[2*nd2+1], pah, vl[2], vl[3]);
                    mma_bf16(o[2*nd2+1], pal, vh[2], vh[3]);
                }
            }
        }
        __syncthreads();
    }

    // ---- normalize + hi/lo split store into (B,S,H*D) ----
    const float il0 = 1.f / l0, il1 = 1.f / l1;
    const int srow = rmin + (lane >> 2);
    const int dq   = (lane & 3) << 1;
#pragma unroll
    for (int nf = 0; nf < 16; ++nf) {
        int d = nf * 8 + dq;
        size_t base = (size_t)(b * NS) * ND + (size_t)h * DH + d;
        uint32_t hp, lp;
        hilo2(o[nf][0] * il0, o[nf][1] * il0, hp, lp);
        *reinterpret_cast<uint32_t*>(Oh + base + (size_t)srow * ND) = hp;
        *reinterpret_cast<uint32_t*>(Ol + base + (size_t)srow * ND) = lp;
        hilo2(o[nf][2] * il1, o[nf][3] * il1, hp, lp);
        *reinterpret_cast<uint32_t*>(Oh + base + (size_t)(srow + 8) * ND) = hp;
        *reinterpret_cast<uint32_t*>(Ol + base + (size_t)(srow + 8) * ND) = lp;
    }
}

// ---------------------------------------------------------------------------
extern "C" void kernel_launch(void* const* d_in, const int* in_sizes, int n_in,
                              void* d_out, int out_size) {
    const float* x  = (const float*)d_in[0];
    const float* Wq = (const float*)d_in[1];
    const float* Wk = (const float*)d_in[2];
    const float* Wv = (const float*)d_in[3];
    const float* Wo = (const float*)d_in[4];

    __nv_bfloat16 *xh, *xl, *wh, *wl, *qh, *ql, *kh, *kl, *vth, *vtl;
    cudaGetSymbolAddress((void**)&xh,  g_xh);
    cudaGetSymbolAddress((void**)&xl,  g_xl);
    cudaGetSymbolAddress((void**)&wh,  g_wh);
    cudaGetSymbolAddress((void**)&wl,  g_wl);
    cudaGetSymbolAddress((void**)&qh,  g_qh);
    cudaGetSymbolAddress((void**)&ql,  g_ql);
    cudaGetSymbolAddress((void**)&kh,  g_kh);
    cudaGetSymbolAddress((void**)&kl,  g_kl);
    cudaGetSymbolAddress((void**)&vth, g_vth);
    cudaGetSymbolAddress((void**)&vtl, g_vtl);

    cudaFuncSetAttribute(gemm_hmma<0>, cudaFuncAttributeMaxDynamicSharedMemorySize, GSMEM);
    cudaFuncSetAttribute(gemm_hmma<1>, cudaFuncAttributeMaxDynamicSharedMemorySize, GSMEM);
    cudaFuncSetAttribute(gemm_hmma<2>, cudaFuncAttributeMaxDynamicSharedMemorySize, GSMEM);
    cudaFuncSetAttribute(gemm_hmma<3>, cudaFuncAttributeMaxDynamicSharedMemorySize, GSMEM);
    cudaFuncSetAttribute(flash_mma,    cudaFuncAttributeMaxDynamicSharedMemorySize, FSMEM);

    dim3 gg(ND / 128, NM / 128);
    dim3 tg(ND / 32, ND / 32);
    dim3 tb(32, 8);
    const int actblocks = NM * ND / (256 * 4);

    split_act<<<actblocks, 256>>>(x, xh, xl);

    split_wT<<<tg, tb>>>(Wq, wh, wl);
    gemm_hmma<0><<<gg, 256, GSMEM>>>(xh, xl, wh, wl, nullptr, qh, ql);
    split_wT<<<tg, tb>>>(Wk, wh, wl);
    gemm_hmma<1><<<gg, 256, GSMEM>>>(xh, xl, wh, wl, nullptr, kh, kl);
    split_wT<<<tg, tb>>>(Wv, wh, wl);
    gemm_hmma<2><<<gg, 256, GSMEM>>>(xh, xl, wh, wl, nullptr, vth, vtl);

    // flash overwrites xh/xl (x is fully consumed by the three GEMMs above)
    flash_mma<<<dim3(NS / 128, NH, NB), 256, FSMEM>>>(qh, ql, kh, kl, vth, vtl, xh, xl);

    split_wT<<<tg, tb>>>(Wo, wh, wl);
    gemm_hmma<3><<<gg, 256, GSMEM>>>(xh, xl, wh, wl, (float*)d_out, nullptr, nullptr);
}

// round 11
// speedup vs baseline: 3.2275x; 1.1276x over previous
#include <cuda_runtime.h>
#include <cuda_bf16.h>
#include <math.h>
#include <math_constants.h>
#include <cstdint>

// Problem constants
#define NB 2
#define NS 2048
#define ND 2048
#define NH 16
#define DH 128
#define NM 4096   // NB*NS

#define L2_10K_OVER_64 0.2076205059304602f   // log2(10000)/64
#define QSCALE 0.08838834764831845f          // 1/sqrt(128)

// Scratch: sanctioned __device__ globals (no runtime allocation).
__device__ __nv_bfloat16 g_xh [NM*ND];         // activation hi (x, then attn-out)
__device__ __nv_bfloat16 g_xl [NM*ND];         // activation lo
__device__ __nv_bfloat16 g_wh [4*ND*ND];       // transposed weights hi [w][n][k]
__device__ __nv_bfloat16 g_wl [4*ND*ND];       // transposed weights lo
__device__ __nv_bfloat16 g_qh [NB*NH*NS*DH];   // Q hi  (B,H,S,D), roped+scaled
__device__ __nv_bfloat16 g_ql [NB*NH*NS*DH];
__device__ __nv_bfloat16 g_kh [NB*NH*NS*DH];   // K hi  (B,H,S,D), roped
__device__ __nv_bfloat16 g_kl [NB*NH*NS*DH];
__device__ __nv_bfloat16 g_vth[NB*NH*DH*NS];   // V^T hi (B,H,D,S)
__device__ __nv_bfloat16 g_vtl[NB*NH*DH*NS];

struct OutPtrs {
    __nv_bfloat16 *qh, *ql, *kh, *kl, *vth, *vtl;
};

// ============================ PTX helpers ==================================
__device__ __forceinline__ uint32_t smem_u32(const void* p) {
    uint32_t a;
    asm("{ .reg .u64 t; cvta.to.shared.u64 t, %1; cvt.u32.u64 %0, t; }"
        : "=r"(a) : "l"(p));
    return a;
}

__device__ __forceinline__ void ldsm4(uint32_t* r, uint32_t addr) {
    asm volatile("ldmatrix.sync.aligned.m8n8.x4.shared.b16 {%0,%1,%2,%3}, [%4];"
        : "=r"(r[0]), "=r"(r[1]), "=r"(r[2]), "=r"(r[3]) : "r"(addr));
}

__device__ __forceinline__ void mma_bf16(float* c, const uint32_t* a,
                                         uint32_t b0, uint32_t b1) {
    asm volatile(
        "mma.sync.aligned.m16n8k16.row.col.f32.bf16.bf16.f32 "
        "{%0,%1,%2,%3}, {%4,%5,%6,%7}, {%8,%9}, {%0,%1,%2,%3};"
        : "+f"(c[0]), "+f"(c[1]), "+f"(c[2]), "+f"(c[3])
        : "r"(a[0]), "r"(a[1]), "r"(a[2]), "r"(a[3]), "r"(b0), "r"(b1));
}

__device__ __forceinline__ void cpa16(uint32_t saddr, const void* gaddr) {
    asm volatile("cp.async.cg.shared.global [%0], [%1], 16;"
                 :: "r"(saddr), "l"(gaddr));
}
#define CPA_COMMIT() asm volatile("cp.async.commit_group;")
#define CPA_WAIT1()  asm volatile("cp.async.wait_group 1;")
#define CPA_WAIT0()  asm volatile("cp.async.wait_group 0;")

// pack (a,b) into bf16x2 hi word + bf16x2 lo-residual word
__device__ __forceinline__ void hilo2(float a, float b, uint32_t& hi, uint32_t& lo) {
    __nv_bfloat16 ha = __float2bfloat16_rn(a);
    __nv_bfloat16 hb = __float2bfloat16_rn(b);
    __nv_bfloat162 hp(ha, hb);
    __nv_bfloat162 lp = __floats2bfloat162_rn(a - __bfloat162float(ha),
                                              b - __bfloat162float(hb));
    hi = *reinterpret_cast<uint32_t*>(&hp);
    lo = *reinterpret_cast<uint32_t*>(&lp);
}

// =========================== split kernels =================================
__global__ void __launch_bounds__(256) split_act(const float* __restrict__ in,
                                                 __nv_bfloat16* __restrict__ hi,
                                                 __nv_bfloat16* __restrict__ lo) {
    int i = (blockIdx.x * 256 + threadIdx.x) * 4;
    float4 v = *(const float4*)(in + i);
    uint32_t h0, l0, h1, l1;
    hilo2(v.x, v.y, h0, l0);
    hilo2(v.z, v.w, h1, l1);
    *(uint2*)(hi + i) = make_uint2(h0, h1);
    *(uint2*)(lo + i) = make_uint2(l0, l1);
}

// All four W[k][n] fp32 -> Wt hi/lo bf16 [w][n][k] in ONE launch (grid.z = w)
__global__ void __launch_bounds__(256) split_wT4(
    const float* __restrict__ W0, const float* __restrict__ W1,
    const float* __restrict__ W2, const float* __restrict__ W3,
    __nv_bfloat16* __restrict__ th, __nv_bfloat16* __restrict__ tl) {
    __shared__ float t[32][33];
    const int w  = blockIdx.z;
    const float* W = (w == 0) ? W0 : (w == 1) ? W1 : (w == 2) ? W2 : W3;
    const size_t wo = (size_t)w * ND * ND;
    const int bx = blockIdx.x * 32;   // n tile
    const int by = blockIdx.y * 32;   // k tile
    const int tx = threadIdx.x, ty = threadIdx.y;
#pragma unroll
    for (int j = ty; j < 32; j += 8)
        t[j][tx] = W[(size_t)(by + j) * ND + bx + tx];
    __syncthreads();
#pragma unroll
    for (int j = ty; j < 32; j += 8) {
        float v = t[tx][j];           // = W[by+tx][bx+j]
        __nv_bfloat16 h = __float2bfloat16_rn(v);
        __nv_bfloat16 l = __float2bfloat16_rn(v - __bfloat162float(h));
        th[wo + (size_t)(bx + j) * ND + by + tx] = h;
        tl[wo + (size_t)(bx + j) * ND + by + tx] = l;
    }
}

// ===================== HMMA bf16x3 GEMM mainloop ===========================
#define APITCH 80
#define TILE_BYTES (128 * APITCH)
#define STAGE_BYTES (4 * TILE_BYTES)
#define GSMEM (2 * STAGE_BYTES)            // 81920

// Arow/Brow pre-offset to the CTA tile's first row; row stride ND.
__device__ __forceinline__ void mma_mainloop(
    float acc[2][8][4],
    const __nv_bfloat16* __restrict__ ArowH, const __nv_bfloat16* __restrict__ ArowL,
    const __nv_bfloat16* __restrict__ BrowH, const __nv_bfloat16* __restrict__ BrowL,
    uint32_t sbase, int tid, int wm, int wn, int lane)
{
    auto load_stage = [&](int buf, int k0) {
#pragma unroll
        for (int t = 0; t < 8; ++t) {
            int id   = tid + t * 256;
            int tile = id >> 9;
            int rem  = id & 511;
            int r    = rem >> 2;
            int c    = rem & 3;
            uint32_t so = sbase + buf * STAGE_BYTES + tile * TILE_BYTES
                        + r * APITCH + c * 16;
            const __nv_bfloat16* g;
            if      (tile == 0) g = ArowH + (size_t)r * ND + k0 + c * 8;
            else if (tile == 1) g = ArowL + (size_t)r * ND + k0 + c * 8;
            else if (tile == 2) g = BrowH + (size_t)r * ND + k0 + c * 8;
            else                g = BrowL + (size_t)r * ND + k0 + c * 8;
            cpa16(so, g);
        }
        CPA_COMMIT();
    };

    load_stage(0, 0);

    for (int it = 0; it < 64; ++it) {
        const int buf = it & 1;
        if (it + 1 < 64) { load_stage(buf ^ 1, (it + 1) * 32); CPA_WAIT1(); }
        else             { CPA_WAIT0(); }
        __syncthreads();

        const uint32_t sA  = sbase + buf * STAGE_BYTES;
        const uint32_t sAl = sA + TILE_BYTES;
        const uint32_t sB  = sA + 2 * TILE_BYTES;
        const uint32_t sBl = sA + 3 * TILE_BYTES;

#pragma unroll
        for (int ks = 0; ks < 2; ++ks) {
            const int akb = ks * 32 + (lane >> 4) * 16;
            uint32_t ah[2][4], al[2][4];
#pragma unroll
            for (int mf = 0; mf < 2; ++mf) {
                uint32_t ro = (wm * 32 + mf * 16 + (lane & 15)) * APITCH + akb;
                ldsm4(ah[mf], sA  + ro);
                ldsm4(al[mf], sAl + ro);
            }
            const int brow = wn * 64 + (lane & 7) + ((lane >> 4) << 3);
            const int bkb  = ks * 32 + ((lane >> 3) & 1) * 16;
#pragma unroll
            for (int nf2 = 0; nf2 < 4; ++nf2) {
                uint32_t bo = (brow + nf2 * 16) * APITCH + bkb;
                uint32_t bh[4], bl[4];
                ldsm4(bh, sB  + bo);
                ldsm4(bl, sBl + bo);
#pragma unroll
                for (int half = 0; half < 2; ++half) {
                    uint32_t h0 = bh[half * 2], h1 = bh[half * 2 + 1];
                    uint32_t l0 = bl[half * 2], l1 = bl[half * 2 + 1];
                    int nf = nf2 * 2 + half;
#pragma unroll
                    for (int mf = 0; mf < 2; ++mf) {
                        mma_bf16(acc[mf][nf], ah[mf], h0, h1);
                        mma_bf16(acc[mf][nf], ah[mf], l0, l1);
                        mma_bf16(acc[mf][nf], al[mf], h0, h1);
                    }
                }
            }
        }
        __syncthreads();
    }
}

// ---- merged Q/K/V projections: grid.x = 48 (mode = blockIdx.x >> 4) ----
__global__ void __launch_bounds__(256, 2) gemm_qkv(
    const __nv_bfloat16* __restrict__ Ah, const __nv_bfloat16* __restrict__ Al,
    const __nv_bfloat16* __restrict__ Wh, const __nv_bfloat16* __restrict__ Wl,
    OutPtrs op)
{
    extern __shared__ char smc[];
    const uint32_t sbase = smem_u32(smc);
    const int tid  = threadIdx.x;
    const int wid  = tid >> 5;
    const int lane = tid & 31;
    const int wm   = wid & 3;
    const int wn   = wid >> 2;
    const int mode = blockIdx.x >> 4;              // 0=Q 1=K 2=V
    const int col0 = (blockIdx.x & 15) * 128;
    const int row0 = blockIdx.y * 128;
    const size_t wo = (size_t)mode * ND * ND;

    float acc[2][8][4];
#pragma unroll
    for (int mf = 0; mf < 2; ++mf)
#pragma unroll
        for (int nf = 0; nf < 8; ++nf)
#pragma unroll
            for (int e = 0; e < 4; ++e) acc[mf][nf][e] = 0.f;

    mma_mainloop(acc, Ah + (size_t)row0 * ND, Al + (size_t)row0 * ND,
                 Wh + wo + (size_t)col0 * ND, Wl + wo + (size_t)col0 * ND,
                 sbase, tid, wm, wn, lane);

    __nv_bfloat16* Ch = (mode == 0) ? op.qh : (mode == 1) ? op.kh : op.vth;
    __nv_bfloat16* Cl = (mode == 0) ? op.ql : (mode == 1) ? op.kl : op.vtl;

#pragma unroll
    for (int mf = 0; mf < 2; ++mf) {
        const int mrow = row0 + wm * 32 + mf * 16 + (lane >> 2);
#pragma unroll
        for (int rr = 0; rr < 2; ++rr) {
            const int m  = mrow + rr * 8;
            const int bb = m >> 11, ss = m & 2047;
#pragma unroll
            for (int nf = 0; nf < 8; ++nf) {
                const int cloc = wn * 64 + nf * 8 + ((lane & 3) << 1);
                const int col  = col0 + cloc;
                const int h    = col >> 7;
                const int d    = cloc & 127;
                float v0 = acc[mf][nf][rr * 2 + 0];
                float v1 = acc[mf][nf][rr * 2 + 1];
                if (mode == 2) {
                    size_t vb = ((size_t)(bb * NH + h) * DH + d) * NS + ss;
                    __nv_bfloat16 h0 = __float2bfloat16_rn(v0);
                    __nv_bfloat16 h1 = __float2bfloat16_rn(v1);
                    Ch[vb]      = h0;
                    Ch[vb + NS] = h1;
                    Cl[vb]      = __float2bfloat16_rn(v0 - __bfloat162float(h0));
                    Cl[vb + NS] = __float2bfloat16_rn(v1 - __bfloat162float(h1));
                } else {
                    size_t ob = (((size_t)(bb * NH + h) * NS + ss) << 7) + d;
                    float pos  = (float)ss;
                    float inv0 = exp2f(-(float)( d      & 63) * L2_10K_OVER_64);
                    float inv1 = exp2f(-(float)((d + 1) & 63) * L2_10K_OVER_64);
                    float s0, c0, s1, c1;
                    sincosf(pos * inv0, &s0, &c0);
                    sincosf(pos * inv1, &s1, &c1);
                    float o0 = v0 * c0 - v1 * s0;
                    float o1 = v1 * c1 + v0 * s1;
                    if (mode == 0) { o0 *= QSCALE; o1 *= QSCALE; }
                    uint32_t hp, lp;
                    hilo2(o0, o1, hp, lp);
                    *reinterpret_cast<uint32_t*>(Ch + ob) = hp;
                    *reinterpret_cast<uint32_t*>(Cl + ob) = lp;
                }
            }
        }
    }
}

// ---- final projection: fp32 row-major out ----
__global__ void __launch_bounds__(256, 2) gemm_out(
    const __nv_bfloat16* __restrict__ Ah, const __nv_bfloat16* __restrict__ Al,
    const __nv_bfloat16* __restrict__ Wh, const __nv_bfloat16* __restrict__ Wl,
    float* __restrict__ C)
{
    extern __shared__ char smc[];
    const uint32_t sbase = smem_u32(smc);
    const int tid  = threadIdx.x;
    const int wid  = tid >> 5;
    const int lane = tid & 31;
    const int wm   = wid & 3;
    const int wn   = wid >> 2;
    const int col0 = blockIdx.x * 128;
    const int row0 = blockIdx.y * 128;

    float acc[2][8][4];
#pragma unroll
    for (int mf = 0; mf < 2; ++mf)
#pragma unroll
        for (int nf = 0; nf < 8; ++nf)
#pragma unroll
            for (int e = 0; e < 4; ++e) acc[mf][nf][e] = 0.f;

    mma_mainloop(acc, Ah + (size_t)row0 * ND, Al + (size_t)row0 * ND,
                 Wh + (size_t)col0 * ND, Wl + (size_t)col0 * ND,
                 sbase, tid, wm, wn, lane);

#pragma unroll
    for (int mf = 0; mf < 2; ++mf) {
        const int mrow = row0 + wm * 32 + mf * 16 + (lane >> 2);
#pragma unroll
        for (int rr = 0; rr < 2; ++rr) {
            const int m = mrow + rr * 8;
#pragma unroll
            for (int nf = 0; nf < 8; ++nf) {
                const int col = col0 + wn * 64 + nf * 8 + ((lane & 3) << 1);
                *(float2*)(C + (size_t)m * ND + col) =
                    make_float2(acc[mf][nf][rr * 2 + 0], acc[mf][nf][rr * 2 + 1]);
            }
        }
    }
}

// ======================= flash attention (mma.sync) ========================
// Unchanged from round 10 (known-good).
#define QPB 272
#define VPB 144
#define OQH 0
#define OQL (OQH + 128*QPB)
#define OKH (OQL + 128*QPB)
#define OKL (OKH + 2*64*QPB)
#define OVH (OKL + 2*64*QPB)
#define OVL (OVH + 2*128*VPB)
#define FSMEM (OVL + 2*128*VPB)       // 212992

__global__ void __launch_bounds__(256, 1) flash_mma(
    const __nv_bfloat16* __restrict__ Qh, const __nv_bfloat16* __restrict__ Ql,
    const __nv_bfloat16* __restrict__ Kh, const __nv_bfloat16* __restrict__ Kl,
    const __nv_bfloat16* __restrict__ Vth, const __nv_bfloat16* __restrict__ Vtl,
    __nv_bfloat16* __restrict__ Oh, __nv_bfloat16* __restrict__ Ol)
{
    extern __shared__ char smc[];
    const uint32_t sb = smem_u32(smc);
    const int tid = threadIdx.x, wid = tid >> 5, lane = tid & 31;
    const int qt = gridDim.x - 1 - blockIdx.x;
    const int q0 = qt * 128;
    const int h  = blockIdx.y, b = blockIdx.z;
    const size_t ho = (size_t)(b * NH + h) * NS * DH;

#pragma unroll
    for (int t = 0; t < 16; ++t) {
        int id  = tid + t * 256;
        int arr = id >> 11;
        int rem = id & 2047;
        int r = rem >> 4, c = rem & 15;
        uint32_t so = sb + (arr ? OQL : OQH) + r * QPB + c * 16;
        const __nv_bfloat16* g = (arr ? Ql : Qh) + ho + (size_t)(q0 + r) * DH + c * 8;
        cpa16(so, g);
    }

    auto loadKV = [&](int buf, int n0) {
#pragma unroll
        for (int t = 0; t < 8; ++t) {
            int id  = tid + t * 256;
            int arr = id >> 10;
            int rem = id & 1023;
            int r = rem >> 4, c = rem & 15;
            uint32_t so = sb + (arr ? OKL : OKH) + buf * (64 * QPB) + r * QPB + c * 16;
            const __nv_bfloat16* g = (arr ? Kl : Kh) + ho + (size_t)(n0 + r) * DH + c * 8;
            cpa16(so, g);
        }
#pragma unroll
        for (int t = 0; t < 8; ++t) {
            int id  = tid + t * 256;
            int arr = id >> 10;
            int rem = id & 1023;
            int r = rem >> 3, c = rem & 7;
            uint32_t so = sb + (arr ? OVL : OVH) + buf * (128 * VPB) + r * VPB + c * 16;
            const __nv_bfloat16* g = (arr ? Vtl : Vth) + ho + (size_t)r * NS + n0 + c * 8;
            cpa16(so, g);
        }
    };

    loadKV(0, 0);
    CPA_COMMIT();

    const int rmin = q0 + wid * 16;
    float o[16][4];
#pragma unroll
    for (int nf = 0; nf < 16; ++nf)
#pragma unroll
        for (int e = 0; e < 4; ++e) o[nf][e] = 0.f;
    float m0 = -CUDART_INF_F, m1 = -CUDART_INF_F, l0 = 0.f, l1 = 0.f;

    const uint32_t a_off  = (uint32_t)((wid * 16 + (lane & 15)) * QPB + (lane >> 4) * 16);
    const uint32_t b_row  = (uint32_t)((lane & 7) + ((lane >> 4) << 3));
    const uint32_t b_koff = (uint32_t)(((lane >> 3) & 1) * 16);

    const int niter = q0 / 64 + 2;
    for (int it = 0; it < niter; ++it) {
        const int n0 = it * 64, buf = it & 1;
        if (it + 1 < niter) { loadKV(buf ^ 1, (it + 1) * 64); CPA_COMMIT(); CPA_WAIT1(); }
        else                { CPA_WAIT0(); }
        __syncthreads();

        if (n0 <= rmin + 15) {
            float sc[8][4];
#pragma unroll
            for (int nf = 0; nf < 8; ++nf)
#pragma unroll
                for (int e = 0; e < 4; ++e) sc[nf][e] = 0.f;

            const uint32_t kh_b = sb + OKH + buf * (64 * QPB) + b_row * QPB + b_koff;
            const uint32_t kl_b = sb + OKL + buf * (64 * QPB) + b_row * QPB + b_koff;
#pragma unroll
            for (int t = 0; t < 8; ++t) {
                uint32_t ah[4], av[4];
                ldsm4(ah, sb + OQH + a_off + t * 32);
                ldsm4(av, sb + OQL + a_off + t * 32);
#pragma unroll
                for (int nf2 = 0; nf2 < 4; ++nf2) {
                    uint32_t bh[4], bl[4];
                    ldsm4(bh, kh_b + nf2 * (16 * QPB) + t * 32);
                    ldsm4(bl, kl_b + nf2 * (16 * QPB) + t * 32);
                    mma_bf16(sc[2*nf2],   ah, bh[0], bh[1]);
                    mma_bf16(sc[2*nf2],   ah, bl[0], bl[1]);
                    mma_bf16(sc[2*nf2],   av, bh[0], bh[1]);
                    mma_bf16(sc[2*nf2+1], ah, bh[2], bh[3]);
                    mma_bf16(sc[2*nf2+1], ah, bl[2], bl[3]);
                    mma_bf16(sc[2*nf2+1], av, bh[2], bh[3]);
                }
            }

            const int r_lo = rmin + (lane >> 2);
            if (n0 + 63 > rmin) {
#pragma unroll
                for (int nf = 0; nf < 8; ++nf) {
                    int cbase = n0 + nf * 8 + ((lane & 3) << 1);
#pragma unroll
                    for (int e = 0; e < 4; ++e) {
                        int col = cbase + (e & 1);
                        int row = r_lo + ((e >> 1) << 3);
                        if (col > row) sc[nf][e] = -CUDART_INF_F;
                    }
                }
            }

            float mx0 = -CUDART_INF_F, mx1 = -CUDART_INF_F;
#pragma unroll
            for (int nf = 0; nf < 8; ++nf) {
                mx0 = fmaxf(mx0, fmaxf(sc[nf][0], sc[nf][1]));
                mx1 = fmaxf(mx1, fmaxf(sc[nf][2], sc[nf][3]));
            }
            mx0 = fmaxf(mx0, __shfl_xor_sync(0xffffffffu, mx0, 1));
            mx0 = fmaxf(mx0, __shfl_xor_sync(0xffffffffu, mx0, 2));
            mx1 = fmaxf(mx1, __shfl_xor_sync(0xffffffffu, mx1, 1));
            mx1 = fmaxf(mx1, __shfl_xor_sync(0xffffffffu, mx1, 2));
            float mn0 = fmaxf(m0, mx0), mn1 = fmaxf(m1, mx1);
            float al0 = __expf(m0 - mn0), al1 = __expf(m1 - mn1);
            float rs0 = 0.f, rs1 = 0.f;
#pragma unroll
            for (int nf = 0; nf < 8; ++nf) {
                sc[nf][0] = __expf(sc[nf][0] - mn0);
                sc[nf][1] = __expf(sc[nf][1] - mn0);
                sc[nf][2] = __expf(sc[nf][2] - mn1);
                sc[nf][3] = __expf(sc[nf][3] - mn1);
                rs0 += sc[nf][0] + sc[nf][1];
                rs1 += sc[nf][2] + sc[nf][3];
            }
            rs0 += __shfl_xor_sync(0xffffffffu, rs0, 1);
            rs0 += __shfl_xor_sync(0xffffffffu, rs0, 2);
            rs1 += __shfl_xor_sync(0xffffffffu, rs1, 1);
            rs1 += __shfl_xor_sync(0xffffffffu, rs1, 2);
            l0 = l0 * al0 + rs0;  l1 = l1 * al1 + rs1;
            m0 = mn0;             m1 = mn1;
#pragma unroll
            for (int nf = 0; nf < 16; ++nf) {
                o[nf][0] *= al0; o[nf][1] *= al0;
                o[nf][2] *= al1; o[nf][3] *= al1;
            }

            const uint32_t vh_b = sb + OVH + buf * (128 * VPB) + b_row * VPB + b_koff;
            const uint32_t vl_b = sb + OVL + buf * (128 * VPB) + b_row * VPB + b_koff;
#pragma unroll
            for (int t = 0; t < 4; ++t) {
                uint32_t pah[4], pal[4];
                hilo2(sc[2*t][0],   sc[2*t][1],   pah[0], pal[0]);
                hilo2(sc[2*t][2],   sc[2*t][3],   pah[1], pal[1]);
                hilo2(sc[2*t+1][0], sc[2*t+1][1], pah[2], pal[2]);
                hilo2(sc[2*t+1][2], sc[2*t+1][3], pah[3], pal[3]);
#pragma unroll
                for (int nd2 = 0; nd2 < 8; ++nd2) {
                    uint32_t vh[4], vl[4];
                    ldsm4(vh, vh_b + nd2 * (16 * VPB) + t * 32);
                    ldsm4(vl, vl_b + nd2 * (16 * VPB) + t * 32);
                    mma_bf16(o[2*nd2],   pah, vh[0], vh[1]);
                    mma_bf16(o[2*nd2],   pah, vl[0], vl[1]);
                    mma_bf16(o[2*nd2],   pal, vh[0], vh[1]);
                    mma_bf16(o[2*nd2+1], pah, vh[2], vh[3]);
                    mma_bf16(o[2*nd2+1], pah, vl[2], vl[3]);
                    mma_bf16(o[2*nd2+1], pal, vh[2], vh[3]);
                }
            }
        }
        __syncthreads();
    }

    const float il0 = 1.f / l0, il1 = 1.f / l1;
    const int srow = rmin + (lane >> 2);
    const int dq   = (lane & 3) << 1;
#pragma unroll
    for (int nf = 0; nf < 16; ++nf) {
        int d = nf * 8 + dq;
        size_t base = (size_t)(b * NS) * ND + (size_t)h * DH + d;
        uint32_t hp, lp;
        hilo2(o[nf][0] * il0, o[nf][1] * il0, hp, lp);
        *reinterpret_cast<uint32_t*>(Oh + base + (size_t)srow * ND) = hp;
        *reinterpret_cast<uint32_t*>(Ol + base + (size_t)srow * ND) = lp;
        hilo2(o[nf][2] * il1, o[nf][3] * il1, hp, lp);
        *reinterpret_cast<uint32_t*>(Oh + base + (size_t)(srow + 8) * ND) = hp;
        *reinterpret_cast<uint32_t*>(Ol + base + (size_t)(srow + 8) * ND) = lp;
    }
}

// ---------------------------------------------------------------------------
extern "C" void kernel_launch(void* const* d_in, const int* in_sizes, int n_in,
                              void* d_out, int out_size) {
    const float* x  = (const float*)d_in[0];
    const float* Wq = (const float*)d_in[1];
    const float* Wk = (const float*)d_in[2];
    const float* Wv = (const float*)d_in[3];
    const float* Wo = (const float*)d_in[4];

    __nv_bfloat16 *xh, *xl, *wh, *wl, *qh, *ql, *kh, *kl, *vth, *vtl;
    cudaGetSymbolAddress((void**)&xh,  g_xh);
    cudaGetSymbolAddress((void**)&xl,  g_xl);
    cudaGetSymbolAddress((void**)&wh,  g_wh);
    cudaGetSymbolAddress((void**)&wl,  g_wl);
    cudaGetSymbolAddress((void**)&qh,  g_qh);
    cudaGetSymbolAddress((void**)&ql,  g_ql);
    cudaGetSymbolAddress((void**)&kh,  g_kh);
    cudaGetSymbolAddress((void**)&kl,  g_kl);
    cudaGetSymbolAddress((void**)&vth, g_vth);
    cudaGetSymbolAddress((void**)&vtl, g_vtl);

    cudaFuncSetAttribute(gemm_qkv, cudaFuncAttributeMaxDynamicSharedMemorySize, GSMEM);
    cudaFuncSetAttribute(gemm_out, cudaFuncAttributeMaxDynamicSharedMemorySize, GSMEM);
    cudaFuncSetAttribute(flash_mma, cudaFuncAttributeMaxDynamicSharedMemorySize, FSMEM);

    OutPtrs op{qh, ql, kh, kl, vth, vtl};

    const int actblocks = NM * ND / (256 * 4);

    // Independent prep: activation split + all four weight transpose-splits.
    split_act<<<actblocks, 256>>>(x, xh, xl);
    split_wT4<<<dim3(ND / 32, ND / 32, 4), dim3(32, 8)>>>(Wq, Wk, Wv, Wo, wh, wl);

    // Merged Q/K/V projections (one launch, 1536 CTAs).
    gemm_qkv<<<dim3(48, NM / 128), 256, GSMEM>>>(xh, xl, wh, wl, op);

    // Flash attention writes bf16 hi/lo attn-out into xh/xl.
    flash_mma<<<dim3(NS / 128, NH, NB), 256, FSMEM>>>(qh, ql, kh, kl, vth, vtl, xh, xl);

    // Final projection (weight index 3).
    gemm_out<<<dim3(ND / 128, NM / 128), 256, GSMEM>>>(
        xh, xl, wh + (size_t)3 * ND * ND, wl + (size_t)3 * ND * ND, (float*)d_out);
}